// round 3
// baseline (speedup 1.0000x reference)
#include <cuda_runtime.h>
#include <math.h>

#define NN 50000
#define EE 800000
#define ETOT (NN + EE)

typedef unsigned long long ull;

__device__ float g_A[NN * 128];
__device__ float g_B[NN * 128];
__device__ float g_asrc[NN * 4];
__device__ float g_adst[NN * 4];
__device__ int   g_counts[NN];
__device__ int   g_rowptr[NN + 1];
__device__ int   g_cursor[NN];
__device__ int   g_col[ETOT];
__device__ int   g_part[256];
__device__ int   g_part_scan[256];

// ---------------- packed f32x2 helpers ----------------

__device__ __forceinline__ ull pack2(float x) {
    ull r;
    asm("mov.b64 %0, {%1, %1};" : "=l"(r) : "f"(x));
    return r;
}
__device__ __forceinline__ void ffma2(ull& d, ull a, ull b) {
    asm("fma.rn.f32x2 %0, %1, %2, %0;" : "+l"(d) : "l"(a), "l"(b));
}
__device__ __forceinline__ float2 unpack2(ull v) {
    float2 f;
    asm("mov.b64 {%0, %1}, %2;" : "=f"(f.x), "=f"(f.y) : "l"(v));
    return f;
}

// ---------------- CSR build ----------------

__global__ void zero_counts_kernel() {
    int i = blockIdx.x * blockDim.x + threadIdx.x;
    if (i < NN) g_counts[i] = 0;
}

__global__ void count_kernel(const int* __restrict__ ei, int E, int etot) {
    int i = blockIdx.x * blockDim.x + threadIdx.x;
    if (i >= etot) return;
    int dst = (i < E) ? ei[E + i] : (i - E);
    atomicAdd(&g_counts[dst], 1);
}

__device__ __forceinline__ int block_excl_scan(int v, int tid) {
    __shared__ int ws[8];
    int lane = tid & 31, wid = tid >> 5;
    int x = v;
    #pragma unroll
    for (int o = 1; o < 32; o <<= 1) {
        int t = __shfl_up_sync(0xffffffffu, x, o);
        if (lane >= o) x += t;
    }
    if (lane == 31) ws[wid] = x;
    __syncthreads();
    if (wid == 0) {
        int w = (lane < 8) ? ws[lane] : 0;
        #pragma unroll
        for (int o = 1; o < 8; o <<= 1) {
            int t = __shfl_up_sync(0xffffffffu, w, o);
            if (lane >= o) w += t;
        }
        if (lane < 8) ws[lane] = w;
    }
    __syncthreads();
    return x - v + (wid ? ws[wid - 1] : 0);
}

__global__ void reduce_kernel() {
    int tid = threadIdx.x;
    int i = blockIdx.x * 256 + tid;
    int v = (i < NN) ? g_counts[i] : 0;
    #pragma unroll
    for (int o = 16; o > 0; o >>= 1) v += __shfl_down_sync(0xffffffffu, v, o);
    __shared__ int ws[8];
    if ((tid & 31) == 0) ws[tid >> 5] = v;
    __syncthreads();
    if (tid == 0) {
        int s = 0;
        #pragma unroll
        for (int w = 0; w < 8; w++) s += ws[w];
        g_part[blockIdx.x] = s;
    }
}

__global__ void scanp_kernel(int nb) {
    int tid = threadIdx.x;
    int v = (tid < nb) ? g_part[tid] : 0;
    int e = block_excl_scan(v, tid);
    if (tid < nb) g_part_scan[tid] = e;
}

__global__ void scanf_kernel(int etot) {
    int tid = threadIdx.x;
    int i = blockIdx.x * 256 + tid;
    int v = (i < NN) ? g_counts[i] : 0;
    int e = block_excl_scan(v, tid) + g_part_scan[blockIdx.x];
    if (i < NN) { g_rowptr[i] = e; g_cursor[i] = e; }
    if (i == 0) g_rowptr[NN] = etot;
}

__global__ void fill_kernel(const int* __restrict__ ei, int E, int etot) {
    int i = blockIdx.x * blockDim.x + threadIdx.x;
    if (i >= etot) return;
    int s, d;
    if (i < E) { s = ei[i]; d = ei[E + i]; }
    else       { s = i - E; d = i - E; }
    int p = atomicAdd(&g_cursor[d], 1);
    g_col[p] = s;
}

// ---------------- Fast 128x128 linear (layers 0/1) ----------------

__global__ void lin128_kernel(const float* __restrict__ X, const float* __restrict__ W,
                              const float* __restrict__ a_s, const float* __restrict__ a_d,
                              float* __restrict__ Hout, float* __restrict__ asrc,
                              float* __restrict__ adst, int nrows) {
    extern __shared__ float sm[];
    float* Ws = sm;              // [128][128]
    float* Xt = sm + 128 * 128;  // [128][66] transposed
    int tid = threadIdx.x;
    int row0 = blockIdx.x * 64;

    {
        const float4* Wg = (const float4*)W;
        float4* Wsh = (float4*)Ws;
        for (int i = tid; i < 128 * 32; i += 256) Wsh[i] = Wg[i];
    }
    for (int i = tid; i < 64 * 128; i += 256) {
        int m = i >> 7, k = i & 127;
        float v = (row0 + m < nrows) ? X[(row0 + m) * 128 + k] : 0.f;
        Xt[k * 66 + m] = v;
    }
    __syncthreads();

    int tn = tid & 31, tm = tid >> 5;
    int n0 = tn * 4, m0 = tm * 8;

    ull acc[4][4];
    #pragma unroll
    for (int p = 0; p < 4; p++)
        #pragma unroll
        for (int j = 0; j < 4; j++) acc[p][j] = 0ULL;

    const float* wp = Ws + n0;
    const float* xp = Xt + m0;
    #pragma unroll 4
    for (int k = 0; k < 128; k++) {
        float4 bv = *(const float4*)(wp + k * 128);
        ull b0 = pack2(bv.x), b1 = pack2(bv.y), b2 = pack2(bv.z), b3 = pack2(bv.w);
        const ull* ap = (const ull*)(xp + k * 66);
        ull a0 = ap[0], a1 = ap[1], a2 = ap[2], a3 = ap[3];
        ffma2(acc[0][0], a0, b0); ffma2(acc[0][1], a0, b1);
        ffma2(acc[0][2], a0, b2); ffma2(acc[0][3], a0, b3);
        ffma2(acc[1][0], a1, b0); ffma2(acc[1][1], a1, b1);
        ffma2(acc[1][2], a1, b2); ffma2(acc[1][3], a1, b3);
        ffma2(acc[2][0], a2, b0); ffma2(acc[2][1], a2, b1);
        ffma2(acc[2][2], a2, b2); ffma2(acc[2][3], a2, b3);
        ffma2(acc[3][0], a3, b0); ffma2(acc[3][1], a3, b1);
        ffma2(acc[3][2], a3, b2); ffma2(acc[3][3], a3, b3);
    }

    float va0 = a_s[n0], va1 = a_s[n0 + 1], va2 = a_s[n0 + 2], va3 = a_s[n0 + 3];
    float vd0 = a_d[n0], vd1 = a_d[n0 + 1], vd2 = a_d[n0 + 2], vd3 = a_d[n0 + 3];
    int head = tn >> 3;

    #pragma unroll
    for (int p = 0; p < 4; p++) {
        float2 f0 = unpack2(acc[p][0]), f1 = unpack2(acc[p][1]);
        float2 f2 = unpack2(acc[p][2]), f3 = unpack2(acc[p][3]);
        #pragma unroll
        for (int h = 0; h < 2; h++) {
            int row = row0 + m0 + 2 * p + h;
            float v0 = h ? f0.y : f0.x;
            float v1 = h ? f1.y : f1.x;
            float v2 = h ? f2.y : f2.x;
            float v3 = h ? f3.y : f3.x;
            bool valid = (row < nrows);
            if (valid) {
                float4 o = make_float4(v0, v1, v2, v3);
                *(float4*)(Hout + row * 128 + n0) = o;
            }
            float ss = v0 * va0 + v1 * va1 + v2 * va2 + v3 * va3;
            float sd = v0 * vd0 + v1 * vd1 + v2 * vd2 + v3 * vd3;
            #pragma unroll
            for (int o = 1; o < 8; o <<= 1) {
                ss += __shfl_xor_sync(0xffffffffu, ss, o);
                sd += __shfl_xor_sync(0xffffffffu, sd, o);
            }
            if (valid && (tn & 7) == 0) {
                asrc[row * 4 + head] = ss;
                adst[row * 4 + head] = sd;
            }
        }
    }
}

// ---------------- Linear layer 2 (K=128, COUT=40), register-tiled ----------------
// Block 320 threads: tm = tid&7 (8 row-groups x 8 rows = 64 rows), tn = tid>>3 (40 cols)

__global__ void lin40_kernel(const float* __restrict__ X, const float* __restrict__ W,
                             const float* __restrict__ a_s, const float* __restrict__ a_d,
                             float* __restrict__ Hout, float* __restrict__ asrc,
                             float* __restrict__ adst, int nrows) {
    extern __shared__ float sm[];
    float* Ws = sm;              // [128][40]
    float* Xt = Ws + 128 * 40;   // [128][66]
    float* red_s = Xt + 128 * 66;  // [64]
    float* red_d = red_s + 64;     // [64]
    int tid = threadIdx.x;
    int row0 = blockIdx.x * 64;

    for (int i = tid; i < 128 * 40; i += 320) Ws[i] = W[i];
    for (int i = tid; i < 64 * 128; i += 320) {
        int m = i >> 7, k = i & 127;
        float v = (row0 + m < nrows) ? X[(row0 + m) * 128 + k] : 0.f;
        Xt[k * 66 + m] = v;
    }
    if (tid < 64) { red_s[tid] = 0.f; red_d[tid] = 0.f; }
    __syncthreads();

    int tm = tid & 7, tn = tid >> 3;
    int m0 = tm * 8;

    ull acc[4];
    #pragma unroll
    for (int j = 0; j < 4; j++) acc[j] = 0ULL;

    #pragma unroll 4
    for (int k = 0; k < 128; k++) {
        ull bw = pack2(Ws[k * 40 + tn]);
        const ull* ap = (const ull*)(Xt + k * 66 + m0);
        ffma2(acc[0], ap[0], bw);
        ffma2(acc[1], ap[1], bw);
        ffma2(acc[2], ap[2], bw);
        ffma2(acc[3], ap[3], bw);
    }

    float va = a_s[tn], vd = a_d[tn];
    float pss = 0.f, psd = 0.f;   // per-thread partials per row, reduced below
    #pragma unroll
    for (int p = 0; p < 4; p++) {
        float2 f = unpack2(acc[p]);
        #pragma unroll
        for (int h = 0; h < 2; h++) {
            int row = row0 + m0 + 2 * p + h;
            float v = h ? f.y : f.x;
            if (row < nrows) Hout[row * 40 + tn] = v;
            // reduce v*va over tn within warp: lanes with same tm differ by 8,16
            float ss = v * va, sd = v * vd;
            ss += __shfl_xor_sync(0xffffffffu, ss, 8);
            ss += __shfl_xor_sync(0xffffffffu, ss, 16);
            sd += __shfl_xor_sync(0xffffffffu, sd, 8);
            sd += __shfl_xor_sync(0xffffffffu, sd, 16);
            if ((tid & 31) < 8) {
                atomicAdd(&red_s[m0 + 2 * p + h], ss);
                atomicAdd(&red_d[m0 + 2 * p + h], sd);
            }
            (void)pss; (void)psd;
        }
    }
    __syncthreads();
    if (tid < 64) {
        int row = row0 + tid;
        if (row < nrows) {
            asrc[row * 4] = red_s[tid];
            adst[row * 4] = red_d[tid];
        }
    }
}

// ---------------- Aggregation layers 0/1: warp per node, two-phase softmax ----------------

__global__ void agg_kernel(const float* __restrict__ Hin, const float* __restrict__ asrc,
                           const float* __restrict__ adst, const float* __restrict__ bias,
                           float* __restrict__ Hout) {
    int node = (blockIdx.x * blockDim.x + threadIdx.x) >> 5;
    if (node >= NN) return;
    int lane = threadIdx.x & 31;
    int head = lane >> 3;
    int s = g_rowptr[node], e = g_rowptr[node + 1];
    float4 ad4 = ((const float4*)adst)[node];

    // phase 1: per-head max (lanes stride edges)
    float m0 = -INFINITY, m1 = -INFINITY, m2 = -INFINITY, m3 = -INFINITY;
    for (int i = s + lane; i < e; i += 32) {
        int src = g_col[i];
        float4 av = ((const float4*)asrc)[src];
        float l0 = av.x + ad4.x; l0 = fmaxf(l0, 0.2f * l0);
        float l1 = av.y + ad4.y; l1 = fmaxf(l1, 0.2f * l1);
        float l2 = av.z + ad4.z; l2 = fmaxf(l2, 0.2f * l2);
        float l3 = av.w + ad4.w; l3 = fmaxf(l3, 0.2f * l3);
        m0 = fmaxf(m0, l0); m1 = fmaxf(m1, l1);
        m2 = fmaxf(m2, l2); m3 = fmaxf(m3, l3);
    }
    #pragma unroll
    for (int o = 16; o > 0; o >>= 1) {
        m0 = fmaxf(m0, __shfl_xor_sync(0xffffffffu, m0, o));
        m1 = fmaxf(m1, __shfl_xor_sync(0xffffffffu, m1, o));
        m2 = fmaxf(m2, __shfl_xor_sync(0xffffffffu, m2, o));
        m3 = fmaxf(m3, __shfl_xor_sync(0xffffffffu, m3, o));
    }
    float mh = (head == 0) ? m0 : (head == 1) ? m1 : (head == 2) ? m2 : m3;
    float adh = (head == 0) ? ad4.x : (head == 1) ? ad4.y : (head == 2) ? ad4.z : ad4.w;

    // phase 2: single pass, independent exps
    float ssum = 0.f, a0 = 0.f, a1 = 0.f, a2 = 0.f, a3 = 0.f;
    #pragma unroll 2
    for (int i = s; i < e; i++) {
        int src = g_col[i];
        float lg = asrc[src * 4 + head] + adh;
        lg = fmaxf(lg, 0.2f * lg);
        float ce = __expf(lg - mh);
        float4 h = *(const float4*)(Hin + src * 128 + lane * 4);
        ssum += ce;
        a0 = fmaf(ce, h.x, a0);
        a1 = fmaf(ce, h.y, a1);
        a2 = fmaf(ce, h.z, a2);
        a3 = fmaf(ce, h.w, a3);
    }
    float inv = 1.f / (ssum + 1e-16f);
    float4 b4 = *(const float4*)(bias + lane * 4);
    float o0 = a0 * inv + b4.x;
    float o1 = a1 * inv + b4.y;
    float o2 = a2 * inv + b4.z;
    float o3 = a3 * inv + b4.w;
    o0 = o0 > 0.f ? o0 : expm1f(o0);
    o1 = o1 > 0.f ? o1 : expm1f(o1);
    o2 = o2 > 0.f ? o2 : expm1f(o2);
    o3 = o3 > 0.f ? o3 : expm1f(o3);
    *(float4*)(Hout + node * 128 + lane * 4) = make_float4(o0, o1, o2, o3);
}

// ---------------- Aggregation layer 2: warp per node, 1 head, 40 ch, log_softmax ----------------

__global__ void agg2_kernel(const float* __restrict__ Hin, const float* __restrict__ asrc,
                            const float* __restrict__ adst, const float* __restrict__ bias,
                            float* __restrict__ out) {
    int node = (blockIdx.x * blockDim.x + threadIdx.x) >> 5;
    if (node >= NN) return;
    int lane = threadIdx.x & 31;
    int s = g_rowptr[node], e = g_rowptr[node + 1];
    float ad = adst[node * 4];

    float mh = -INFINITY;
    for (int i = s + lane; i < e; i += 32) {
        int src = g_col[i];
        float lg = asrc[src * 4] + ad;
        lg = fmaxf(lg, 0.2f * lg);
        mh = fmaxf(mh, lg);
    }
    #pragma unroll
    for (int o = 16; o > 0; o >>= 1) mh = fmaxf(mh, __shfl_xor_sync(0xffffffffu, mh, o));

    float ssum = 0.f, acc0 = 0.f, acc1 = 0.f;
    #pragma unroll 2
    for (int i = s; i < e; i++) {
        int src = g_col[i];
        float lg = asrc[src * 4] + ad;
        lg = fmaxf(lg, 0.2f * lg);
        float ce = __expf(lg - mh);
        ssum += ce;
        acc0 = fmaf(ce, Hin[src * 40 + lane], acc0);
        if (lane < 8) acc1 = fmaf(ce, Hin[src * 40 + 32 + lane], acc1);
    }
    float inv = 1.f / (ssum + 1e-16f);
    float v0 = acc0 * inv + bias[lane];
    float v1 = (lane < 8) ? (acc1 * inv + bias[32 + lane]) : -INFINITY;
    float mx = fmaxf(v0, v1);
    #pragma unroll
    for (int o = 16; o > 0; o >>= 1) mx = fmaxf(mx, __shfl_xor_sync(0xffffffffu, mx, o));
    float se = __expf(v0 - mx) + ((lane < 8) ? __expf(v1 - mx) : 0.f);
    #pragma unroll
    for (int o = 16; o > 0; o >>= 1) se += __shfl_xor_sync(0xffffffffu, se, o);
    float lse = mx + logf(se);
    out[node * 40 + lane] = v0 - lse;
    if (lane < 8) out[node * 40 + 32 + lane] = v1 - lse;
}

// ---------------- host ----------------

extern "C" void kernel_launch(void* const* d_in, const int* in_sizes, int n_in,
                              void* d_out, int out_size) {
    const float* x   = (const float*)d_in[0];
    const int*   ei  = (const int*)d_in[1];
    const float* W0  = (const float*)d_in[2];
    const float* as0 = (const float*)d_in[3];
    const float* ad0 = (const float*)d_in[4];
    const float* b0  = (const float*)d_in[5];
    const float* W1  = (const float*)d_in[6];
    const float* as1 = (const float*)d_in[7];
    const float* ad1 = (const float*)d_in[8];
    const float* b1  = (const float*)d_in[9];
    const float* W2  = (const float*)d_in[10];
    const float* as2 = (const float*)d_in[11];
    const float* ad2 = (const float*)d_in[12];
    const float* b2  = (const float*)d_in[13];
    float* out = (float*)d_out;

    int E = in_sizes[1] / 2;
    int etot = E + NN;

    float *A, *B, *asrc, *adst;
    cudaGetSymbolAddress((void**)&A, g_A);
    cudaGetSymbolAddress((void**)&B, g_B);
    cudaGetSymbolAddress((void**)&asrc, g_asrc);
    cudaGetSymbolAddress((void**)&adst, g_adst);

    const int NB = (NN + 255) / 256;  // 196

    zero_counts_kernel<<<NB, 256>>>();
    count_kernel<<<(etot + 255) / 256, 256>>>(ei, E, etot);
    reduce_kernel<<<NB, 256>>>();
    scanp_kernel<<<1, 256>>>(NB);
    scanf_kernel<<<NB, 256>>>(etot);
    fill_kernel<<<(etot + 255) / 256, 256>>>(ei, E, etot);

    const int smem_lin128 = (128 * 128 + 128 * 66) * 4;         // 99328
    const int smem_lin40  = (128 * 40 + 128 * 66 + 128) * 4;    // 54784
    cudaFuncSetAttribute(lin128_kernel, cudaFuncAttributeMaxDynamicSharedMemorySize, smem_lin128);
    cudaFuncSetAttribute(lin40_kernel, cudaFuncAttributeMaxDynamicSharedMemorySize, smem_lin40);

    int lin_grid = (NN + 63) / 64;            // 782
    int agg_grid = (NN * 32 + 255) / 256;     // warp per node

    // layer 0
    lin128_kernel<<<lin_grid, 256, smem_lin128>>>(x, W0, as0, ad0, A, asrc, adst, NN);
    agg_kernel<<<agg_grid, 256>>>(A, asrc, adst, b0, B);
    // layer 1
    lin128_kernel<<<lin_grid, 256, smem_lin128>>>(B, W1, as1, ad1, A, asrc, adst, NN);
    agg_kernel<<<agg_grid, 256>>>(A, asrc, adst, b1, B);
    // layer 2 (asrc/adst written at stride 4, head 0)
    lin40_kernel<<<lin_grid, 320, smem_lin40>>>(B, W2, as2, ad2, A, asrc, adst, NN);
    agg2_kernel<<<agg_grid, 256>>>(A, asrc, adst, b2, out);

    (void)n_in; (void)out_size;
}

// round 6
// speedup vs baseline: 1.0289x; 1.0289x over previous
#include <cuda_runtime.h>
#include <cuda_fp16.h>
#include <math.h>

#define NN 50000
#define EE 800000
#define ETOT (NN + EE)

typedef unsigned long long ull;

__device__ __half g_H16[NN * 128];   // fp16 messages (gather operand)
__device__ float  g_B[NN * 128];     // fp32 layer activations (GEMM input)
__device__ float  g_asrc[NN * 4];
__device__ float  g_adst[NN * 4];
__device__ int    g_counts[NN];
__device__ int    g_rowptr[NN + 1];
__device__ int    g_cursor[NN];
__device__ int    g_col[ETOT];
__device__ int    g_part[256];
__device__ int    g_part_scan[256];

// ---------------- packed f32x2 helpers ----------------

__device__ __forceinline__ ull pack2(float x) {
    ull r;
    asm("mov.b64 %0, {%1, %1};" : "=l"(r) : "f"(x));
    return r;
}
__device__ __forceinline__ void ffma2(ull& d, ull a, ull b) {
    asm("fma.rn.f32x2 %0, %1, %2, %0;" : "+l"(d) : "l"(a), "l"(b));
}
__device__ __forceinline__ float2 unpack2(ull v) {
    float2 f;
    asm("mov.b64 {%0, %1}, %2;" : "=f"(f.x), "=f"(f.y) : "l"(v));
    return f;
}

// ---------------- CSR build ----------------

__global__ void count_kernel(const int* __restrict__ ei, int E, int etot) {
    int i = blockIdx.x * blockDim.x + threadIdx.x;
    if (i >= etot) return;
    int dst = (i < E) ? ei[E + i] : (i - E);
    atomicAdd(&g_counts[dst], 1);
}

__device__ __forceinline__ int block_excl_scan(int v, int tid) {
    __shared__ int ws[8];
    int lane = tid & 31, wid = tid >> 5;
    int x = v;
    #pragma unroll
    for (int o = 1; o < 32; o <<= 1) {
        int t = __shfl_up_sync(0xffffffffu, x, o);
        if (lane >= o) x += t;
    }
    if (lane == 31) ws[wid] = x;
    __syncthreads();
    if (wid == 0) {
        int w = (lane < 8) ? ws[lane] : 0;
        #pragma unroll
        for (int o = 1; o < 8; o <<= 1) {
            int t = __shfl_up_sync(0xffffffffu, w, o);
            if (lane >= o) w += t;
        }
        if (lane < 8) ws[lane] = w;
    }
    __syncthreads();
    return x - v + (wid ? ws[wid - 1] : 0);
}

__global__ void reduce_kernel() {
    int tid = threadIdx.x;
    int i = blockIdx.x * 256 + tid;
    int v = (i < NN) ? g_counts[i] : 0;
    #pragma unroll
    for (int o = 16; o > 0; o >>= 1) v += __shfl_down_sync(0xffffffffu, v, o);
    __shared__ int ws[8];
    if ((tid & 31) == 0) ws[tid >> 5] = v;
    __syncthreads();
    if (tid == 0) {
        int s = 0;
        #pragma unroll
        for (int w = 0; w < 8; w++) s += ws[w];
        g_part[blockIdx.x] = s;
    }
}

__global__ void scanp_kernel(int nb) {
    int tid = threadIdx.x;
    int v = (tid < nb) ? g_part[tid] : 0;
    int e = block_excl_scan(v, tid);
    if (tid < nb) g_part_scan[tid] = e;
}

__global__ void scanf_kernel(int etot) {
    int tid = threadIdx.x;
    int i = blockIdx.x * 256 + tid;
    int v = (i < NN) ? g_counts[i] : 0;
    int e = block_excl_scan(v, tid) + g_part_scan[blockIdx.x];
    if (i < NN) { g_rowptr[i] = e; g_cursor[i] = e; }
    if (i == 0) g_rowptr[NN] = etot;
}

__global__ void fill_kernel(const int* __restrict__ ei, int E, int etot) {
    int i = blockIdx.x * blockDim.x + threadIdx.x;
    if (i >= etot) return;
    int s, d;
    if (i < E) { s = ei[i]; d = ei[E + i]; }
    else       { s = i - E; d = i - E; }
    int p = atomicAdd(&g_cursor[d], 1);
    g_col[p] = s;
}

// ---------------- Fast 128x128 linear (layers 0/1), fp16 message output ----------------

__global__ void lin128_kernel(const float* __restrict__ X, const float* __restrict__ W,
                              const float* __restrict__ a_s, const float* __restrict__ a_d,
                              __half* __restrict__ H16, float* __restrict__ asrc,
                              float* __restrict__ adst, int nrows) {
    extern __shared__ float sm[];
    float* Ws = sm;              // [128][128]
    float* Xt = sm + 128 * 128;  // [128][66] transposed
    int tid = threadIdx.x;
    int row0 = blockIdx.x * 64;

    {
        const float4* Wg = (const float4*)W;
        float4* Wsh = (float4*)Ws;
        for (int i = tid; i < 128 * 32; i += 256) Wsh[i] = Wg[i];
    }
    for (int i = tid; i < 64 * 128; i += 256) {
        int m = i >> 7, k = i & 127;
        float v = (row0 + m < nrows) ? X[(row0 + m) * 128 + k] : 0.f;
        Xt[k * 66 + m] = v;
    }
    __syncthreads();

    int tn = tid & 31, tm = tid >> 5;
    int n0 = tn * 4, m0 = tm * 8;

    ull acc[4][4];
    #pragma unroll
    for (int p = 0; p < 4; p++)
        #pragma unroll
        for (int j = 0; j < 4; j++) acc[p][j] = 0ULL;

    const float* wp = Ws + n0;
    const float* xp = Xt + m0;
    #pragma unroll 4
    for (int k = 0; k < 128; k++) {
        float4 bv = *(const float4*)(wp + k * 128);
        ull b0 = pack2(bv.x), b1 = pack2(bv.y), b2 = pack2(bv.z), b3 = pack2(bv.w);
        const ull* ap = (const ull*)(xp + k * 66);
        ull a0 = ap[0], a1 = ap[1], a2 = ap[2], a3 = ap[3];
        ffma2(acc[0][0], a0, b0); ffma2(acc[0][1], a0, b1);
        ffma2(acc[0][2], a0, b2); ffma2(acc[0][3], a0, b3);
        ffma2(acc[1][0], a1, b0); ffma2(acc[1][1], a1, b1);
        ffma2(acc[1][2], a1, b2); ffma2(acc[1][3], a1, b3);
        ffma2(acc[2][0], a2, b0); ffma2(acc[2][1], a2, b1);
        ffma2(acc[2][2], a2, b2); ffma2(acc[2][3], a2, b3);
        ffma2(acc[3][0], a3, b0); ffma2(acc[3][1], a3, b1);
        ffma2(acc[3][2], a3, b2); ffma2(acc[3][3], a3, b3);
    }

    float va0 = a_s[n0], va1 = a_s[n0 + 1], va2 = a_s[n0 + 2], va3 = a_s[n0 + 3];
    float vd0 = a_d[n0], vd1 = a_d[n0 + 1], vd2 = a_d[n0 + 2], vd3 = a_d[n0 + 3];
    int head = tn >> 3;

    #pragma unroll
    for (int p = 0; p < 4; p++) {
        float2 f0 = unpack2(acc[p][0]), f1 = unpack2(acc[p][1]);
        float2 f2 = unpack2(acc[p][2]), f3 = unpack2(acc[p][3]);
        #pragma unroll
        for (int h = 0; h < 2; h++) {
            int row = row0 + m0 + 2 * p + h;
            float v0 = h ? f0.y : f0.x;
            float v1 = h ? f1.y : f1.x;
            float v2 = h ? f2.y : f2.x;
            float v3 = h ? f3.y : f3.x;
            bool valid = (row < nrows);
            if (valid) {
                __half2 p0 = __floats2half2_rn(v0, v1);
                __half2 p1 = __floats2half2_rn(v2, v3);
                uint2 u;
                u.x = *(unsigned*)&p0;
                u.y = *(unsigned*)&p1;
                *(uint2*)(H16 + row * 128 + n0) = u;
            }
            float ss = v0 * va0 + v1 * va1 + v2 * va2 + v3 * va3;
            float sd = v0 * vd0 + v1 * vd1 + v2 * vd2 + v3 * vd3;
            #pragma unroll
            for (int o = 1; o < 8; o <<= 1) {
                ss += __shfl_xor_sync(0xffffffffu, ss, o);
                sd += __shfl_xor_sync(0xffffffffu, sd, o);
            }
            if (valid && (tn & 7) == 0) {
                asrc[row * 4 + head] = ss;
                adst[row * 4 + head] = sd;
            }
        }
    }
}

// ---------------- Linear layer 2 (K=128, COUT=40), fp16 output ----------------

__global__ void lin40_kernel(const float* __restrict__ X, const float* __restrict__ W,
                             const float* __restrict__ a_s, const float* __restrict__ a_d,
                             __half* __restrict__ H16, float* __restrict__ asrc,
                             float* __restrict__ adst, int nrows) {
    extern __shared__ float sm[];
    float* Ws = sm;                 // [128][40]
    float* Xt = Ws + 128 * 40;      // [128][66]
    float* red_s = Xt + 128 * 66;   // [64]
    float* red_d = red_s + 64;      // [64]
    int tid = threadIdx.x;
    int row0 = blockIdx.x * 64;

    for (int i = tid; i < 128 * 40; i += 320) Ws[i] = W[i];
    for (int i = tid; i < 64 * 128; i += 320) {
        int m = i >> 7, k = i & 127;
        float v = (row0 + m < nrows) ? X[(row0 + m) * 128 + k] : 0.f;
        Xt[k * 66 + m] = v;
    }
    if (tid < 64) { red_s[tid] = 0.f; red_d[tid] = 0.f; }
    __syncthreads();

    int tm = tid & 7, tn = tid >> 3;
    int m0 = tm * 8;

    ull acc[4];
    #pragma unroll
    for (int j = 0; j < 4; j++) acc[j] = 0ULL;

    #pragma unroll 4
    for (int k = 0; k < 128; k++) {
        ull bw = pack2(Ws[k * 40 + tn]);
        const ull* ap = (const ull*)(Xt + k * 66 + m0);
        ffma2(acc[0], ap[0], bw);
        ffma2(acc[1], ap[1], bw);
        ffma2(acc[2], ap[2], bw);
        ffma2(acc[3], ap[3], bw);
    }

    float va = a_s[tn], vd = a_d[tn];
    #pragma unroll
    for (int p = 0; p < 4; p++) {
        float2 f = unpack2(acc[p]);
        #pragma unroll
        for (int h = 0; h < 2; h++) {
            int row = row0 + m0 + 2 * p + h;
            float v = h ? f.y : f.x;
            if (row < nrows) H16[row * 40 + tn] = __float2half_rn(v);
            float ss = v * va, sd = v * vd;
            ss += __shfl_xor_sync(0xffffffffu, ss, 8);
            ss += __shfl_xor_sync(0xffffffffu, ss, 16);
            sd += __shfl_xor_sync(0xffffffffu, sd, 8);
            sd += __shfl_xor_sync(0xffffffffu, sd, 16);
            if ((tid & 31) < 8) {
                atomicAdd(&red_s[m0 + 2 * p + h], ss);
                atomicAdd(&red_d[m0 + 2 * p + h], sd);
            }
        }
    }
    __syncthreads();
    if (tid < 64) {
        int row = row0 + tid;
        if (row < nrows) {
            asrc[row * 4] = red_s[tid];
            adst[row * 4] = red_d[tid];
        }
    }
}

// ---------------- Aggregation layers 0/1: warp per node, fp16 gathers ----------------

__global__ void agg_kernel(const __half* __restrict__ H16, const float* __restrict__ asrc,
                           const float* __restrict__ adst, const float* __restrict__ bias,
                           float* __restrict__ Hout) {
    int node = (blockIdx.x * blockDim.x + threadIdx.x) >> 5;
    if (node >= NN) return;
    int lane = threadIdx.x & 31;
    int head = lane >> 3;
    int s = g_rowptr[node], e = g_rowptr[node + 1];
    float4 ad4 = ((const float4*)adst)[node];

    // phase 1: per-head max (lanes stride edges)
    float m0 = -INFINITY, m1 = -INFINITY, m2 = -INFINITY, m3 = -INFINITY;
    for (int i = s + lane; i < e; i += 32) {
        int src = g_col[i];
        float4 av = ((const float4*)asrc)[src];
        float l0 = av.x + ad4.x; l0 = fmaxf(l0, 0.2f * l0);
        float l1 = av.y + ad4.y; l1 = fmaxf(l1, 0.2f * l1);
        float l2 = av.z + ad4.z; l2 = fmaxf(l2, 0.2f * l2);
        float l3 = av.w + ad4.w; l3 = fmaxf(l3, 0.2f * l3);
        m0 = fmaxf(m0, l0); m1 = fmaxf(m1, l1);
        m2 = fmaxf(m2, l2); m3 = fmaxf(m3, l3);
    }
    #pragma unroll
    for (int o = 16; o > 0; o >>= 1) {
        m0 = fmaxf(m0, __shfl_xor_sync(0xffffffffu, m0, o));
        m1 = fmaxf(m1, __shfl_xor_sync(0xffffffffu, m1, o));
        m2 = fmaxf(m2, __shfl_xor_sync(0xffffffffu, m2, o));
        m3 = fmaxf(m3, __shfl_xor_sync(0xffffffffu, m3, o));
    }
    float mh = (head == 0) ? m0 : (head == 1) ? m1 : (head == 2) ? m2 : m3;
    float adh = (head == 0) ? ad4.x : (head == 1) ? ad4.y : (head == 2) ? ad4.z : ad4.w;

    // phase 2: fp16 gather, fp32 accumulate
    float ssum = 0.f, a0 = 0.f, a1 = 0.f, a2 = 0.f, a3 = 0.f;
    #pragma unroll 4
    for (int i = s; i < e; i++) {
        int src = g_col[i];
        float lg = asrc[src * 4 + head] + adh;
        lg = fmaxf(lg, 0.2f * lg);
        float ce = __expf(lg - mh);
        uint2 u = ((const uint2*)(H16 + src * 128))[lane];
        float2 hlo = __half22float2(*(const __half2*)&u.x);
        float2 hhi = __half22float2(*(const __half2*)&u.y);
        ssum += ce;
        a0 = fmaf(ce, hlo.x, a0);
        a1 = fmaf(ce, hlo.y, a1);
        a2 = fmaf(ce, hhi.x, a2);
        a3 = fmaf(ce, hhi.y, a3);
    }
    float inv = 1.f / (ssum + 1e-16f);
    float4 b4 = *(const float4*)(bias + lane * 4);
    float o0 = a0 * inv + b4.x;
    float o1 = a1 * inv + b4.y;
    float o2 = a2 * inv + b4.z;
    float o3 = a3 * inv + b4.w;
    o0 = o0 > 0.f ? o0 : expm1f(o0);
    o1 = o1 > 0.f ? o1 : expm1f(o1);
    o2 = o2 > 0.f ? o2 : expm1f(o2);
    o3 = o3 > 0.f ? o3 : expm1f(o3);
    *(float4*)(Hout + node * 128 + lane * 4) = make_float4(o0, o1, o2, o3);
}

// ---------------- Aggregation layer 2: warp per node, fp16, 20 lanes x 2ch ----------------

__global__ void agg2_kernel(const __half* __restrict__ H16, const float* __restrict__ asrc,
                            const float* __restrict__ adst, const float* __restrict__ bias,
                            float* __restrict__ out) {
    int node = (blockIdx.x * blockDim.x + threadIdx.x) >> 5;
    if (node >= NN) return;
    int lane = threadIdx.x & 31;
    int s = g_rowptr[node], e = g_rowptr[node + 1];
    float ad = adst[node * 4];

    float mh = -INFINITY;
    for (int i = s + lane; i < e; i += 32) {
        int src = g_col[i];
        float lg = asrc[src * 4] + ad;
        lg = fmaxf(lg, 0.2f * lg);
        mh = fmaxf(mh, lg);
    }
    #pragma unroll
    for (int o = 16; o > 0; o >>= 1) mh = fmaxf(mh, __shfl_xor_sync(0xffffffffu, mh, o));

    bool active = (lane < 20);
    float ssum = 0.f, aLo = 0.f, aHi = 0.f;
    #pragma unroll 4
    for (int i = s; i < e; i++) {
        int src = g_col[i];
        float lg = asrc[src * 4] + ad;
        lg = fmaxf(lg, 0.2f * lg);
        float ce = __expf(lg - mh);
        ssum += ce;
        if (active) {
            unsigned u = *(const unsigned*)(H16 + src * 40 + lane * 2);
            float2 hv = __half22float2(*(const __half2*)&u);
            aLo = fmaf(ce, hv.x, aLo);
            aHi = fmaf(ce, hv.y, aHi);
        }
    }
    float inv = 1.f / (ssum + 1e-16f);
    float vLo = active ? (aLo * inv + bias[lane * 2])     : -INFINITY;
    float vHi = active ? (aHi * inv + bias[lane * 2 + 1]) : -INFINITY;
    float mx = fmaxf(vLo, vHi);
    #pragma unroll
    for (int o = 16; o > 0; o >>= 1) mx = fmaxf(mx, __shfl_xor_sync(0xffffffffu, mx, o));
    float se = active ? (__expf(vLo - mx) + __expf(vHi - mx)) : 0.f;
    #pragma unroll
    for (int o = 16; o > 0; o >>= 1) se += __shfl_xor_sync(0xffffffffu, se, o);
    float lse = mx + logf(se);
    if (active) {
        float2 r = make_float2(vLo - lse, vHi - lse);
        *(float2*)(out + node * 40 + lane * 2) = r;
    }
}

// ---------------- host ----------------

extern "C" void kernel_launch(void* const* d_in, const int* in_sizes, int n_in,
                              void* d_out, int out_size) {
    const float* x   = (const float*)d_in[0];
    const int*   ei  = (const int*)d_in[1];
    const float* W0  = (const float*)d_in[2];
    const float* as0 = (const float*)d_in[3];
    const float* ad0 = (const float*)d_in[4];
    const float* b0  = (const float*)d_in[5];
    const float* W1  = (const float*)d_in[6];
    const float* as1 = (const float*)d_in[7];
    const float* ad1 = (const float*)d_in[8];
    const float* b1  = (const float*)d_in[9];
    const float* W2  = (const float*)d_in[10];
    const float* as2 = (const float*)d_in[11];
    const float* ad2 = (const float*)d_in[12];
    const float* b2  = (const float*)d_in[13];
    float* out = (float*)d_out;

    int E = in_sizes[1] / 2;
    int etot = E + NN;

    __half* H16;
    float *B, *asrc, *adst;
    int* counts;
    cudaGetSymbolAddress((void**)&H16, g_H16);
    cudaGetSymbolAddress((void**)&B, g_B);
    cudaGetSymbolAddress((void**)&asrc, g_asrc);
    cudaGetSymbolAddress((void**)&adst, g_adst);
    cudaGetSymbolAddress((void**)&counts, g_counts);

    const int NB = (NN + 255) / 256;  // 196

    cudaMemsetAsync(counts, 0, NN * sizeof(int));
    count_kernel<<<(etot + 511) / 512, 512>>>(ei, E, etot);
    reduce_kernel<<<NB, 256>>>();
    scanp_kernel<<<1, 256>>>(NB);
    scanf_kernel<<<NB, 256>>>(etot);
    fill_kernel<<<(etot + 511) / 512, 512>>>(ei, E, etot);

    const int smem_lin128 = (128 * 128 + 128 * 66) * 4;         // 99328
    const int smem_lin40  = (128 * 40 + 128 * 66 + 128) * 4;    // 54784
    cudaFuncSetAttribute(lin128_kernel, cudaFuncAttributeMaxDynamicSharedMemorySize, smem_lin128);
    cudaFuncSetAttribute(lin40_kernel, cudaFuncAttributeMaxDynamicSharedMemorySize, smem_lin40);

    int lin_grid = (NN + 63) / 64;            // 782
    int agg_grid = (NN * 32 + 255) / 256;     // warp per node

    // layer 0
    lin128_kernel<<<lin_grid, 256, smem_lin128>>>(x, W0, as0, ad0, H16, asrc, adst, NN);
    agg_kernel<<<agg_grid, 256>>>(H16, asrc, adst, b0, B);
    // layer 1
    lin128_kernel<<<lin_grid, 256, smem_lin128>>>(B, W1, as1, ad1, H16, asrc, adst, NN);
    agg_kernel<<<agg_grid, 256>>>(H16, asrc, adst, b1, B);
    // layer 2
    lin40_kernel<<<lin_grid, 320, smem_lin40>>>(B, W2, as2, ad2, H16, asrc, adst, NN);
    agg2_kernel<<<agg_grid, 256>>>(H16, asrc, adst, b2, out);

    (void)n_in; (void)out_size;
}

// round 7
// speedup vs baseline: 1.0594x; 1.0297x over previous
#include <cuda_runtime.h>
#include <cuda_fp16.h>
#include <math.h>

#define NN 50000
#define EE 800000
#define ETOT (NN + EE)
#define DEGCAP 96

typedef unsigned long long ull;

__device__ __half g_H16[NN * 128];   // fp16 messages (gather operand)
__device__ float  g_B[NN * 128];     // fp32 layer activations (GEMM input)
__device__ float  g_asrc[NN * 4];
__device__ float  g_adst[NN * 4];
__device__ int    g_counts[NN];
__device__ int    g_rowptr[NN + 1];
__device__ int    g_cursor[NN];
__device__ int    g_col[ETOT];
__device__ ull    g_tile[256];       // decoupled lookback: (value<<2)|status

// ---------------- packed f32x2 helpers ----------------

__device__ __forceinline__ ull pack2(float x) {
    ull r;
    asm("mov.b64 %0, {%1, %1};" : "=l"(r) : "f"(x));
    return r;
}
__device__ __forceinline__ void ffma2(ull& d, ull a, ull b) {
    asm("fma.rn.f32x2 %0, %1, %2, %0;" : "+l"(d) : "l"(a), "l"(b));
}
__device__ __forceinline__ float2 unpack2(ull v) {
    float2 f;
    asm("mov.b64 {%0, %1}, %2;" : "=f"(f.x), "=f"(f.y) : "l"(v));
    return f;
}

// ---------------- CSR build ----------------

__global__ void count_kernel(const int* __restrict__ ei, int E, int etot) {
    int i = blockIdx.x * blockDim.x + threadIdx.x;
    if (i >= etot) return;
    int dst = (i < E) ? ei[E + i] : (i - E);
    atomicAdd(&g_counts[dst], 1);
}

__device__ __forceinline__ int block_excl_scan(int v, int tid) {
    __shared__ int ws[8];
    int lane = tid & 31, wid = tid >> 5;
    int x = v;
    #pragma unroll
    for (int o = 1; o < 32; o <<= 1) {
        int t = __shfl_up_sync(0xffffffffu, x, o);
        if (lane >= o) x += t;
    }
    if (lane == 31) ws[wid] = x;
    __syncthreads();
    if (wid == 0) {
        int w = (lane < 8) ? ws[lane] : 0;
        #pragma unroll
        for (int o = 1; o < 8; o <<= 1) {
            int t = __shfl_up_sync(0xffffffffu, w, o);
            if (lane >= o) w += t;
        }
        if (lane < 8) ws[lane] = w;
    }
    __syncthreads();
    return x - v + (wid ? ws[wid - 1] : 0);
}

// single-pass scan with decoupled lookback; writes rowptr + cursor
__global__ void scan_kernel(int etot) {
    int tid = threadIdx.x;
    int b = blockIdx.x;
    int i = b * 256 + tid;
    int v = (i < NN) ? g_counts[i] : 0;
    int excl = block_excl_scan(v, tid);

    __shared__ int sm_total;
    __shared__ int sm_run;
    if (tid == 255) sm_total = excl + v;
    __syncthreads();
    int total = sm_total;

    if (tid < 32) {
        int lane = tid;
        // publish own aggregate (block 0 publishes inclusive prefix directly)
        if (lane == 0) {
            ull word = ((ull)(unsigned)total << 2) | (b == 0 ? 2ULL : 1ULL);
            atomicExch(&g_tile[b], word);
        }
        int running = 0;
        if (b > 0) {
            int p = b - 1;
            while (true) {
                int idx = p - lane;
                int st = 0, val = 0;
                if (idx >= 0) {
                    ull t;
                    do { t = *(volatile ull*)&g_tile[idx]; } while ((t & 3ULL) == 0ULL);
                    st = (int)(t & 3ULL);
                    val = (int)(t >> 2);
                }
                unsigned pmask = __ballot_sync(0xffffffffu, idx >= 0 && st == 2);
                if (pmask) {
                    int firstp = __ffs(pmask) - 1;  // nearest predecessor w/ prefix
                    if (lane > firstp) val = 0;
                    #pragma unroll
                    for (int o = 16; o > 0; o >>= 1) val += __shfl_xor_sync(0xffffffffu, val, o);
                    running += val;
                    break;
                } else {
                    if (idx < 0) val = 0;
                    #pragma unroll
                    for (int o = 16; o > 0; o >>= 1) val += __shfl_xor_sync(0xffffffffu, val, o);
                    running += val;
                    p -= 32;
                }
            }
            if (lane == 0) {
                ull word = ((ull)(unsigned)(running + total) << 2) | 2ULL;
                atomicExch(&g_tile[b], word);
            }
        }
        if (lane == 0) sm_run = running;
    }
    __syncthreads();
    int base = sm_run;
    if (i < NN) { g_rowptr[i] = base + excl; g_cursor[i] = base + excl; }
    if (i == 0) g_rowptr[NN] = etot;
}

__global__ void fill_kernel(const int* __restrict__ ei, int E, int etot) {
    int i = blockIdx.x * blockDim.x + threadIdx.x;
    if (i >= etot) return;
    int s, d;
    if (i < E) { s = ei[i]; d = ei[E + i]; }
    else       { s = i - E; d = i - E; }
    int p = atomicAdd(&g_cursor[d], 1);
    g_col[p] = s;
}

// ---------------- Fast 128x128 linear (layers 0/1), fp16 message output ----------------

__global__ void lin128_kernel(const float* __restrict__ X, const float* __restrict__ W,
                              const float* __restrict__ a_s, const float* __restrict__ a_d,
                              __half* __restrict__ H16, float* __restrict__ asrc,
                              float* __restrict__ adst, int nrows) {
    extern __shared__ float sm[];
    float* Ws = sm;              // [128][128]
    float* Xt = sm + 128 * 128;  // [128][66] transposed
    int tid = threadIdx.x;
    int row0 = blockIdx.x * 64;

    {
        const float4* Wg = (const float4*)W;
        float4* Wsh = (float4*)Ws;
        for (int i = tid; i < 128 * 32; i += 256) Wsh[i] = Wg[i];
    }
    for (int i = tid; i < 64 * 128; i += 256) {
        int m = i >> 7, k = i & 127;
        float v = (row0 + m < nrows) ? X[(row0 + m) * 128 + k] : 0.f;
        Xt[k * 66 + m] = v;
    }
    __syncthreads();

    int tn = tid & 31, tm = tid >> 5;
    int n0 = tn * 4, m0 = tm * 8;

    ull acc[4][4];
    #pragma unroll
    for (int p = 0; p < 4; p++)
        #pragma unroll
        for (int j = 0; j < 4; j++) acc[p][j] = 0ULL;

    const float* wp = Ws + n0;
    const float* xp = Xt + m0;
    #pragma unroll 4
    for (int k = 0; k < 128; k++) {
        float4 bv = *(const float4*)(wp + k * 128);
        ull b0 = pack2(bv.x), b1 = pack2(bv.y), b2 = pack2(bv.z), b3 = pack2(bv.w);
        const ull* ap = (const ull*)(xp + k * 66);
        ull a0 = ap[0], a1 = ap[1], a2 = ap[2], a3 = ap[3];
        ffma2(acc[0][0], a0, b0); ffma2(acc[0][1], a0, b1);
        ffma2(acc[0][2], a0, b2); ffma2(acc[0][3], a0, b3);
        ffma2(acc[1][0], a1, b0); ffma2(acc[1][1], a1, b1);
        ffma2(acc[1][2], a1, b2); ffma2(acc[1][3], a1, b3);
        ffma2(acc[2][0], a2, b0); ffma2(acc[2][1], a2, b1);
        ffma2(acc[2][2], a2, b2); ffma2(acc[2][3], a2, b3);
        ffma2(acc[3][0], a3, b0); ffma2(acc[3][1], a3, b1);
        ffma2(acc[3][2], a3, b2); ffma2(acc[3][3], a3, b3);
    }

    float va0 = a_s[n0], va1 = a_s[n0 + 1], va2 = a_s[n0 + 2], va3 = a_s[n0 + 3];
    float vd0 = a_d[n0], vd1 = a_d[n0 + 1], vd2 = a_d[n0 + 2], vd3 = a_d[n0 + 3];
    int head = tn >> 3;

    #pragma unroll
    for (int p = 0; p < 4; p++) {
        float2 f0 = unpack2(acc[p][0]), f1 = unpack2(acc[p][1]);
        float2 f2 = unpack2(acc[p][2]), f3 = unpack2(acc[p][3]);
        #pragma unroll
        for (int h = 0; h < 2; h++) {
            int row = row0 + m0 + 2 * p + h;
            float v0 = h ? f0.y : f0.x;
            float v1 = h ? f1.y : f1.x;
            float v2 = h ? f2.y : f2.x;
            float v3 = h ? f3.y : f3.x;
            bool valid = (row < nrows);
            if (valid) {
                __half2 p0 = __floats2half2_rn(v0, v1);
                __half2 p1 = __floats2half2_rn(v2, v3);
                uint2 u;
                u.x = *(unsigned*)&p0;
                u.y = *(unsigned*)&p1;
                *(uint2*)(H16 + row * 128 + n0) = u;
            }
            float ss = v0 * va0 + v1 * va1 + v2 * va2 + v3 * va3;
            float sd = v0 * vd0 + v1 * vd1 + v2 * vd2 + v3 * vd3;
            #pragma unroll
            for (int o = 1; o < 8; o <<= 1) {
                ss += __shfl_xor_sync(0xffffffffu, ss, o);
                sd += __shfl_xor_sync(0xffffffffu, sd, o);
            }
            if (valid && (tn & 7) == 0) {
                asrc[row * 4 + head] = ss;
                adst[row * 4 + head] = sd;
            }
        }
    }
}

// ---------------- Linear layer 2 (K=128, COUT=40), fp16 output ----------------

__global__ void lin40_kernel(const float* __restrict__ X, const float* __restrict__ W,
                             const float* __restrict__ a_s, const float* __restrict__ a_d,
                             __half* __restrict__ H16, float* __restrict__ asrc,
                             float* __restrict__ adst, int nrows) {
    extern __shared__ float sm[];
    float* Ws = sm;                 // [128][40]
    float* Xt = Ws + 128 * 40;      // [128][66]
    float* red_s = Xt + 128 * 66;   // [64]
    float* red_d = red_s + 64;      // [64]
    int tid = threadIdx.x;
    int row0 = blockIdx.x * 64;

    for (int i = tid; i < 128 * 40; i += 320) Ws[i] = W[i];
    for (int i = tid; i < 64 * 128; i += 320) {
        int m = i >> 7, k = i & 127;
        float v = (row0 + m < nrows) ? X[(row0 + m) * 128 + k] : 0.f;
        Xt[k * 66 + m] = v;
    }
    if (tid < 64) { red_s[tid] = 0.f; red_d[tid] = 0.f; }
    __syncthreads();

    int tm = tid & 7, tn = tid >> 3;
    int m0 = tm * 8;

    ull acc[4];
    #pragma unroll
    for (int j = 0; j < 4; j++) acc[j] = 0ULL;

    #pragma unroll 4
    for (int k = 0; k < 128; k++) {
        ull bw = pack2(Ws[k * 40 + tn]);
        const ull* ap = (const ull*)(Xt + k * 66 + m0);
        ffma2(acc[0], ap[0], bw);
        ffma2(acc[1], ap[1], bw);
        ffma2(acc[2], ap[2], bw);
        ffma2(acc[3], ap[3], bw);
    }

    float va = a_s[tn], vd = a_d[tn];
    #pragma unroll
    for (int p = 0; p < 4; p++) {
        float2 f = unpack2(acc[p]);
        #pragma unroll
        for (int h = 0; h < 2; h++) {
            int row = row0 + m0 + 2 * p + h;
            float v = h ? f.y : f.x;
            if (row < nrows) H16[row * 40 + tn] = __float2half_rn(v);
            float ss = v * va, sd = v * vd;
            ss += __shfl_xor_sync(0xffffffffu, ss, 8);
            ss += __shfl_xor_sync(0xffffffffu, ss, 16);
            sd += __shfl_xor_sync(0xffffffffu, sd, 8);
            sd += __shfl_xor_sync(0xffffffffu, sd, 16);
            if ((tid & 31) < 8) {
                atomicAdd(&red_s[m0 + 2 * p + h], ss);
                atomicAdd(&red_d[m0 + 2 * p + h], sd);
            }
        }
    }
    __syncthreads();
    if (tid < 64) {
        int row = row0 + tid;
        if (row < nrows) {
            asrc[row * 4] = red_s[tid];
            adst[row * 4] = red_d[tid];
        }
    }
}

// ---------------- Aggregation layers 0/1: warp per node, smem-cached logits ----------------

__global__ void agg_kernel(const __half* __restrict__ H16, const float* __restrict__ asrc,
                           const float* __restrict__ adst, const float* __restrict__ bias,
                           float* __restrict__ Hout) {
    __shared__ int   colbuf[8][DEGCAP];
    __shared__ float lgbuf[8][DEGCAP][4];
    int node = (blockIdx.x * blockDim.x + threadIdx.x) >> 5;
    if (node >= NN) return;
    int lane = threadIdx.x & 31;
    int wip = (threadIdx.x >> 5) & 7;
    int head = lane >> 3;
    int s = g_rowptr[node], e = g_rowptr[node + 1];
    int deg = e - s;
    float4 ad4 = ((const float4*)adst)[node];
    bool fast = (deg <= DEGCAP);

    // phase 1: per-head max; cache (col, logits) in smem on fast path
    float m0 = -INFINITY, m1 = -INFINITY, m2 = -INFINITY, m3 = -INFINITY;
    for (int i = lane; i < deg; i += 32) {
        int src = g_col[s + i];
        float4 av = ((const float4*)asrc)[src];
        float l0 = av.x + ad4.x; l0 = fmaxf(l0, 0.2f * l0);
        float l1 = av.y + ad4.y; l1 = fmaxf(l1, 0.2f * l1);
        float l2 = av.z + ad4.z; l2 = fmaxf(l2, 0.2f * l2);
        float l3 = av.w + ad4.w; l3 = fmaxf(l3, 0.2f * l3);
        if (fast) {
            colbuf[wip][i] = src;
            *(float4*)&lgbuf[wip][i][0] = make_float4(l0, l1, l2, l3);
        }
        m0 = fmaxf(m0, l0); m1 = fmaxf(m1, l1);
        m2 = fmaxf(m2, l2); m3 = fmaxf(m3, l3);
    }
    #pragma unroll
    for (int o = 16; o > 0; o >>= 1) {
        m0 = fmaxf(m0, __shfl_xor_sync(0xffffffffu, m0, o));
        m1 = fmaxf(m1, __shfl_xor_sync(0xffffffffu, m1, o));
        m2 = fmaxf(m2, __shfl_xor_sync(0xffffffffu, m2, o));
        m3 = fmaxf(m3, __shfl_xor_sync(0xffffffffu, m3, o));
    }
    float mh = (head == 0) ? m0 : (head == 1) ? m1 : (head == 2) ? m2 : m3;
    float adh = (head == 0) ? ad4.x : (head == 1) ? ad4.y : (head == 2) ? ad4.z : ad4.w;
    __syncwarp();

    // phase 2
    float ssum = 0.f, a0 = 0.f, a1 = 0.f, a2 = 0.f, a3 = 0.f;
    if (fast) {
        #pragma unroll 4
        for (int i = 0; i < deg; i++) {
            int src = colbuf[wip][i];
            float lg = lgbuf[wip][i][head];
            float ce = __expf(lg - mh);
            uint2 u = ((const uint2*)(H16 + src * 128))[lane];
            float2 hlo = __half22float2(*(const __half2*)&u.x);
            float2 hhi = __half22float2(*(const __half2*)&u.y);
            ssum += ce;
            a0 = fmaf(ce, hlo.x, a0);
            a1 = fmaf(ce, hlo.y, a1);
            a2 = fmaf(ce, hhi.x, a2);
            a3 = fmaf(ce, hhi.y, a3);
        }
    } else {
        #pragma unroll 4
        for (int i = s; i < e; i++) {
            int src = g_col[i];
            float lg = asrc[src * 4 + head] + adh;
            lg = fmaxf(lg, 0.2f * lg);
            float ce = __expf(lg - mh);
            uint2 u = ((const uint2*)(H16 + src * 128))[lane];
            float2 hlo = __half22float2(*(const __half2*)&u.x);
            float2 hhi = __half22float2(*(const __half2*)&u.y);
            ssum += ce;
            a0 = fmaf(ce, hlo.x, a0);
            a1 = fmaf(ce, hlo.y, a1);
            a2 = fmaf(ce, hhi.x, a2);
            a3 = fmaf(ce, hhi.y, a3);
        }
    }
    float inv = 1.f / (ssum + 1e-16f);
    float4 b4 = *(const float4*)(bias + lane * 4);
    float o0 = a0 * inv + b4.x;
    float o1 = a1 * inv + b4.y;
    float o2 = a2 * inv + b4.z;
    float o3 = a3 * inv + b4.w;
    o0 = o0 > 0.f ? o0 : expm1f(o0);
    o1 = o1 > 0.f ? o1 : expm1f(o1);
    o2 = o2 > 0.f ? o2 : expm1f(o2);
    o3 = o3 > 0.f ? o3 : expm1f(o3);
    *(float4*)(Hout + node * 128 + lane * 4) = make_float4(o0, o1, o2, o3);
}

// ---------------- Aggregation layer 2: warp per node, smem-cached logits ----------------

__global__ void agg2_kernel(const __half* __restrict__ H16, const float* __restrict__ asrc,
                            const float* __restrict__ adst, const float* __restrict__ bias,
                            float* __restrict__ out) {
    __shared__ int   colbuf[8][DEGCAP];
    __shared__ float lgbuf[8][DEGCAP];
    int node = (blockIdx.x * blockDim.x + threadIdx.x) >> 5;
    if (node >= NN) return;
    int lane = threadIdx.x & 31;
    int wip = (threadIdx.x >> 5) & 7;
    int s = g_rowptr[node], e = g_rowptr[node + 1];
    int deg = e - s;
    float ad = adst[node * 4];
    bool fast = (deg <= DEGCAP);

    float mh = -INFINITY;
    for (int i = lane; i < deg; i += 32) {
        int src = g_col[s + i];
        float lg = asrc[src * 4] + ad;
        lg = fmaxf(lg, 0.2f * lg);
        if (fast) { colbuf[wip][i] = src; lgbuf[wip][i] = lg; }
        mh = fmaxf(mh, lg);
    }
    #pragma unroll
    for (int o = 16; o > 0; o >>= 1) mh = fmaxf(mh, __shfl_xor_sync(0xffffffffu, mh, o));
    __syncwarp();

    bool active = (lane < 20);
    float ssum = 0.f, aLo = 0.f, aHi = 0.f;
    if (fast) {
        #pragma unroll 4
        for (int i = 0; i < deg; i++) {
            int src = colbuf[wip][i];
            float ce = __expf(lgbuf[wip][i] - mh);
            ssum += ce;
            if (active) {
                unsigned u = *(const unsigned*)(H16 + src * 40 + lane * 2);
                float2 hv = __half22float2(*(const __half2*)&u);
                aLo = fmaf(ce, hv.x, aLo);
                aHi = fmaf(ce, hv.y, aHi);
            }
        }
    } else {
        #pragma unroll 4
        for (int i = s; i < e; i++) {
            int src = g_col[i];
            float lg = asrc[src * 4] + ad;
            lg = fmaxf(lg, 0.2f * lg);
            float ce = __expf(lg - mh);
            ssum += ce;
            if (active) {
                unsigned u = *(const unsigned*)(H16 + src * 40 + lane * 2);
                float2 hv = __half22float2(*(const __half2*)&u);
                aLo = fmaf(ce, hv.x, aLo);
                aHi = fmaf(ce, hv.y, aHi);
            }
        }
    }
    float inv = 1.f / (ssum + 1e-16f);
    float vLo = active ? (aLo * inv + bias[lane * 2])     : -INFINITY;
    float vHi = active ? (aHi * inv + bias[lane * 2 + 1]) : -INFINITY;
    float mx = fmaxf(vLo, vHi);
    #pragma unroll
    for (int o = 16; o > 0; o >>= 1) mx = fmaxf(mx, __shfl_xor_sync(0xffffffffu, mx, o));
    float se = active ? (__expf(vLo - mx) + __expf(vHi - mx)) : 0.f;
    #pragma unroll
    for (int o = 16; o > 0; o >>= 1) se += __shfl_xor_sync(0xffffffffu, se, o);
    float lse = mx + logf(se);
    if (active) {
        float2 r = make_float2(vLo - lse, vHi - lse);
        *(float2*)(out + node * 40 + lane * 2) = r;
    }
}

// ---------------- host ----------------

extern "C" void kernel_launch(void* const* d_in, const int* in_sizes, int n_in,
                              void* d_out, int out_size) {
    const float* x   = (const float*)d_in[0];
    const int*   ei  = (const int*)d_in[1];
    const float* W0  = (const float*)d_in[2];
    const float* as0 = (const float*)d_in[3];
    const float* ad0 = (const float*)d_in[4];
    const float* b0  = (const float*)d_in[5];
    const float* W1  = (const float*)d_in[6];
    const float* as1 = (const float*)d_in[7];
    const float* ad1 = (const float*)d_in[8];
    const float* b1  = (const float*)d_in[9];
    const float* W2  = (const float*)d_in[10];
    const float* as2 = (const float*)d_in[11];
    const float* ad2 = (const float*)d_in[12];
    const float* b2  = (const float*)d_in[13];
    float* out = (float*)d_out;

    int E = in_sizes[1] / 2;
    int etot = E + NN;

    __half* H16;
    float *B, *asrc, *adst;
    int* counts;
    ull* tiles;
    cudaGetSymbolAddress((void**)&H16, g_H16);
    cudaGetSymbolAddress((void**)&B, g_B);
    cudaGetSymbolAddress((void**)&asrc, g_asrc);
    cudaGetSymbolAddress((void**)&adst, g_adst);
    cudaGetSymbolAddress((void**)&counts, g_counts);
    cudaGetSymbolAddress((void**)&tiles, g_tile);

    const int NB = (NN + 255) / 256;  // 196

    cudaMemsetAsync(counts, 0, NN * sizeof(int));
    cudaMemsetAsync(tiles, 0, 256 * sizeof(ull));
    count_kernel<<<(etot + 511) / 512, 512>>>(ei, E, etot);   // kernel 1
    scan_kernel<<<NB, 256>>>(etot);                           // kernel 2
    fill_kernel<<<(etot + 511) / 512, 512>>>(ei, E, etot);    // kernel 3

    const int smem_lin128 = (128 * 128 + 128 * 66) * 4;         // 99328
    const int smem_lin40  = (128 * 40 + 128 * 66 + 128) * 4;    // 54784
    cudaFuncSetAttribute(lin128_kernel, cudaFuncAttributeMaxDynamicSharedMemorySize, smem_lin128);
    cudaFuncSetAttribute(lin40_kernel, cudaFuncAttributeMaxDynamicSharedMemorySize, smem_lin40);

    int lin_grid = (NN + 63) / 64;            // 782
    int agg_grid = (NN * 32 + 255) / 256;     // warp per node

    // layer 0 (lin128 is kernel 4 -> ncu capture target)
    lin128_kernel<<<lin_grid, 256, smem_lin128>>>(x, W0, as0, ad0, H16, asrc, adst, NN);
    agg_kernel<<<agg_grid, 256>>>(H16, asrc, adst, b0, B);
    // layer 1
    lin128_kernel<<<lin_grid, 256, smem_lin128>>>(B, W1, as1, ad1, H16, asrc, adst, NN);
    agg_kernel<<<agg_grid, 256>>>(H16, asrc, adst, b1, B);
    // layer 2
    lin40_kernel<<<lin_grid, 320, smem_lin40>>>(B, W2, as2, ad2, H16, asrc, adst, NN);
    agg2_kernel<<<agg_grid, 256>>>(H16, asrc, adst, b2, out);

    (void)n_in; (void)out_size;
}